// round 10
// baseline (speedup 1.0000x reference)
#include <cuda_runtime.h>
#include <cuda_bf16.h>
#include <cuda_fp16.h>
#include <cstdint>

#define NUM_USERS 100000
#define NUM_ITEMS 100000
#define NUM_NODES (NUM_USERS + NUM_ITEMS)
#define EMB_DIM 64
#define NUM_EDGES 4000000
#define BATCH 4096
#define CHUNKS 16   // 16 float4 per node row (fp32 arrays)

// ---- scratch (device globals: allocation-free) ----
__device__ uint4  g_h1h[NUM_NODES * 8];              // fp16 h1: 64 halves/node = 25.6 MB
__device__ float4 g_h2[NUM_NODES * CHUNKS];          // fp32 h2 (only flagged rows valid)
__device__ uint4  g_embh[NUM_NODES * 8];             // fp16 copy of all_emb, 25.6 MB
__device__ unsigned char g_flag[NUM_NODES];          // batch-row flags (layer2 filter)
__device__ unsigned char g_flag2[NUM_NODES];         // needed-h1-row flags (layer1 filter)
__device__ int4 g_l2[NUM_EDGES];                     // packed {row,col,val,0} layer2 edges
__device__ int g_c2;

__device__ __forceinline__ void red_add_v4_f32(float4* addr, float4 v) {
    asm volatile("red.global.add.v4.f32 [%0], {%1, %2, %3, %4};"
                 :: "l"(addr), "f"(v.x), "f"(v.y), "f"(v.z), "f"(v.w)
                 : "memory");
}

// 16B vectorized fp16 reduction: adds 8 halves (4x half2) atomically.
__device__ __forceinline__ void red_add_v4_f16x2(uint4* addr, uint4 v) {
    asm volatile("red.global.add.noftz.v4.f16x2 [%0], {%1, %2, %3, %4};"
                 :: "l"(addr), "r"(v.x), "r"(v.y), "r"(v.z), "r"(v.w)
                 : "memory");
}

// ---- K0a: zero h1 (fp16) + both flag arrays + counter ----
#define H1H_WORDS (NUM_NODES * 8)                     // 1.6M uint4
#define FLAG_WORDS (NUM_NODES / 16)                   // 12,500 uint4 per flag array
__global__ void k_zero(void) {
    int i = blockIdx.x * blockDim.x + threadIdx.x;
    if (i == 0) g_c2 = 0;
    if (i < H1H_WORDS) {
        g_h1h[i] = make_uint4(0u, 0u, 0u, 0u);
    } else if (i < H1H_WORDS + FLAG_WORDS) {
        ((uint4*)g_flag)[i - H1H_WORDS] = make_uint4(0u, 0u, 0u, 0u);
    } else if (i < H1H_WORDS + 2 * FLAG_WORDS) {
        ((uint4*)g_flag2)[i - H1H_WORDS - FLAG_WORDS] = make_uint4(0u, 0u, 0u, 0u);
    }
}

// ---- K0b: set batch flags (both arrays) + zero those h2 rows ----
__global__ void k_flag(const int* __restrict__ user,
                       const int* __restrict__ pos,
                       const int* __restrict__ neg) {
    int t = blockIdx.x * blockDim.x + threadIdx.x;   // 3*BATCH*16 threads
    int g = t >> 4;
    int c = t & 15;
    if (g >= 3 * BATCH) return;
    int node;
    if (g < BATCH)            node = user[g];
    else if (g < 2 * BATCH)   node = NUM_USERS + pos[g - BATCH];
    else                      node = NUM_USERS + neg[g - 2 * BATCH];
    if (c == 0) { g_flag[node] = 1; g_flag2[node] = 1; }
    g_h2[node * CHUNKS + c] = make_float4(0.f, 0.f, 0.f, 0.f);
}

// ---- K0c: convert all_emb to fp16 (8 floats per thread) ----
#define CVT_GROUPS (NUM_NODES * EMB_DIM / 8)          // 1.6M
#define CVT_USER_GROUPS (NUM_USERS * EMB_DIM / 8)     // 800K
__global__ void k_cvt(const float4* __restrict__ user_emb,
                      const float4* __restrict__ item_emb) {
    int g = blockIdx.x * blockDim.x + threadIdx.x;
    if (g >= CVT_GROUPS) return;
    const float4* src = (g < CVT_USER_GROUPS)
        ? (user_emb + (size_t)g * 2)
        : (item_emb + (size_t)(g - CVT_USER_GROUPS) * 2);
    float4 a = __ldg(src);
    float4 b = __ldg(src + 1);
    __half2 h0 = __floats2half2_rn(a.x, a.y);
    __half2 h1 = __floats2half2_rn(a.z, a.w);
    __half2 h2 = __floats2half2_rn(b.x, b.y);
    __half2 h3 = __floats2half2_rn(b.z, b.w);
    uint4 o;
    o.x = *reinterpret_cast<unsigned*>(&h0);
    o.y = *reinterpret_cast<unsigned*>(&h1);
    o.z = *reinterpret_cast<unsigned*>(&h2);
    o.w = *reinterpret_cast<unsigned*>(&h3);
    g_embh[g] = o;
}

// ---- K_compactA: layer-2 compaction (keep ~6%), conditional col/val loads ----
#define COMPACT_THREADS (NUM_EDGES / 4)               // 1,000,000
__global__ void k_compactA(const int* __restrict__ edge_row,
                           const int* __restrict__ edge_col,
                           const float* __restrict__ edge_val) {
    __shared__ int s_cnt;
    __shared__ int s_base;
    __shared__ int s_warp_off[8];

    const int4*   rows4 = (const int4*)edge_row;
    const int4*   cols4 = (const int4*)edge_col;
    const float4* vals4 = (const float4*)edge_val;

    int t = blockIdx.x * blockDim.x + threadIdx.x;
    int lane = threadIdx.x & 31;
    int warp = threadIdx.x >> 5;
    if (threadIdx.x == 0) s_cnt = 0;
    __syncthreads();

    int4 r = make_int4(0, 0, 0, 0), cc = make_int4(0, 0, 0, 0);
    float4 vv = make_float4(0.f, 0.f, 0.f, 0.f);
    bool k0 = false, k1 = false, k2 = false, k3 = false;
    if (t < COMPACT_THREADS) {
        r  = __ldg(rows4 + t);
        k0 = g_flag[r.x] != 0;
        k1 = g_flag[r.y] != 0;
        k2 = g_flag[r.z] != 0;
        k3 = g_flag[r.w] != 0;
        if (k0 | k1 | k2 | k3) {          // only ~22% of groups touch col/val
            cc = __ldg(cols4 + t);
            vv = __ldg(vals4 + t);
            if (k0) g_flag2[cc.x] = 1;
            if (k1) g_flag2[cc.y] = 1;
            if (k2) g_flag2[cc.z] = 1;
            if (k3) g_flag2[cc.w] = 1;
        }
    }
    int n = (int)k0 + (int)k1 + (int)k2 + (int)k3;
    int pre = n;
    #pragma unroll
    for (int o = 1; o < 32; o <<= 1) {
        int x = __shfl_up_sync(0xFFFFFFFFu, pre, o);
        if (lane >= o) pre += x;
    }
    int excl = pre - n;
    int wtot = __shfl_sync(0xFFFFFFFFu, pre, 31);

    if (lane == 31) s_warp_off[warp] = atomicAdd(&s_cnt, wtot);
    __syncthreads();
    if (threadIdx.x == 0) s_base = atomicAdd(&g_c2, s_cnt);
    __syncthreads();

    int p = s_base + s_warp_off[warp] + excl;
    if (k0) g_l2[p++] = make_int4(r.x, cc.x, __float_as_int(vv.x), 0);
    if (k1) g_l2[p++] = make_int4(r.y, cc.y, __float_as_int(vv.y), 0);
    if (k2) g_l2[p++] = make_int4(r.z, cc.z, __float_as_int(vv.z), 0);
    if (k3) g_l2[p++] = make_int4(r.w, cc.w, __float_as_int(vv.w), 0);
}

// ---- K1: fused-filter SPMM layer 1 over RAW edge arrays ----
// 8 lanes/edge, flag2[row] checked inline; fp16 gather + fp16 vector red.
// Item count is static (NUM_EDGES*8), ILP=4.
#define SPMM1_ITEMS   (NUM_EDGES * 8)                 // 32M
#define SPMM1_THREADS (SPMM1_ITEMS / 4)               // 8M
__global__ void k_spmm1(const int*   __restrict__ edge_row,
                        const int*   __restrict__ edge_col,
                        const float* __restrict__ edge_val) {
    int t = blockIdx.x * blockDim.x + threadIdx.x;
    if (t >= SPMM1_THREADS) return;

    #pragma unroll
    for (int k = 0; k < 4; k++) {
        int item = t + k * SPMM1_THREADS;
        int e = item >> 3;
        int c = item & 7;
        int row = __ldg(edge_row + e);               // 16B/warp, coalesced
        if (g_flag2[row]) {
            int col = __ldg(edge_col + e);
            float v = __ldg(edge_val + e);
            __half2 vh = __float2half2_rn(v);
            uint4 u = __ldg(&g_embh[((size_t)col << 3) + c]);
            __half2 a = *reinterpret_cast<__half2*>(&u.x);
            __half2 b = *reinterpret_cast<__half2*>(&u.y);
            __half2 d = *reinterpret_cast<__half2*>(&u.z);
            __half2 e2 = *reinterpret_cast<__half2*>(&u.w);
            a = __hmul2(a, vh);
            b = __hmul2(b, vh);
            d = __hmul2(d, vh);
            e2 = __hmul2(e2, vh);
            uint4 o;
            o.x = *reinterpret_cast<unsigned*>(&a);
            o.y = *reinterpret_cast<unsigned*>(&b);
            o.z = *reinterpret_cast<unsigned*>(&d);
            o.w = *reinterpret_cast<unsigned*>(&e2);
            red_add_v4_f16x2(&g_h1h[((size_t)row << 3) + c], o);
        }
    }
}

// ---- K2: SPMM layer 2: h2[row] += val * h1h[col] (fp16 gather, fp32 red) ----
__global__ void k_spmm2(void) {
    long long total = (long long)g_c2 * CHUNKS;
    long long stride = (long long)gridDim.x * blockDim.x;
    const uint2* h1 = (const uint2*)g_h1h;   // 4 halves per uint2
    for (long long t = (long long)blockIdx.x * blockDim.x + threadIdx.x;
         t < total; t += stride) {
        int idx = (int)(t >> 4);
        int c = (int)(t & 15);
        int4 m = __ldg(&g_l2[idx]);
        float v = __int_as_float(m.z);
        uint2 u = __ldg(&h1[((size_t)m.y << 4) + c]);
        __half2 ha = *reinterpret_cast<__half2*>(&u.x);
        __half2 hb = *reinterpret_cast<__half2*>(&u.y);
        float2 fa = __half22float2(ha);
        float2 fb = __half22float2(hb);
        float4 acc = make_float4(v * fa.x, v * fa.y, v * fb.x, v * fb.y);
        red_add_v4_f32(&g_h2[(size_t)m.x * CHUNKS + c], acc);
    }
}

// ---- K3: gather acc at batch nodes, dot, write scores ----
__global__ void k_score(const int* __restrict__ user,
                        const int* __restrict__ pos,
                        const int* __restrict__ neg,
                        const float2* __restrict__ user_emb2,
                        const float2* __restrict__ item_emb2,
                        float* __restrict__ out) {
    int w = (blockIdx.x * blockDim.x + threadIdx.x) >> 5;
    int lane = threadIdx.x & 31;
    if (w >= BATCH) return;
    int nu = user[w];
    int np = NUM_USERS + pos[w];
    int nn = NUM_USERS + neg[w];

    const unsigned* h1u = (const unsigned*)g_h1h;   // 2 halves per word
    const float2* h2 = (const float2*)g_h2;
    const int L = EMB_DIM / 2;

    unsigned w1u = __ldg(&h1u[(size_t)nu * L + lane]);
    __half2 hu = *reinterpret_cast<__half2*>(&w1u);
    float2 u1 = __half22float2(hu);
    float2 ue = user_emb2[(size_t)nu * L + lane];
    float2 u2 = h2[(size_t)nu * L + lane];
    float ux = ue.x + u1.x + u2.x;
    float uy = ue.y + u1.y + u2.y;

    unsigned w1p = __ldg(&h1u[(size_t)np * L + lane]);
    __half2 hp = *reinterpret_cast<__half2*>(&w1p);
    float2 p1 = __half22float2(hp);
    float2 pe = item_emb2[(size_t)(np - NUM_USERS) * L + lane];
    float2 p2 = h2[(size_t)np * L + lane];
    float px = pe.x + p1.x + p2.x;
    float py = pe.y + p1.y + p2.y;

    unsigned w1n = __ldg(&h1u[(size_t)nn * L + lane]);
    __half2 hn = *reinterpret_cast<__half2*>(&w1n);
    float2 n1 = __half22float2(hn);
    float2 ne = item_emb2[(size_t)(nn - NUM_USERS) * L + lane];
    float2 n2 = h2[(size_t)nn * L + lane];
    float nx = ne.x + n1.x + n2.x;
    float ny = ne.y + n1.y + n2.y;

    float sp = ux * px + uy * py;
    float sn = ux * nx + uy * ny;
    #pragma unroll
    for (int off = 16; off > 0; off >>= 1) {
        sp += __shfl_xor_sync(0xFFFFFFFFu, sp, off);
        sn += __shfl_xor_sync(0xFFFFFFFFu, sn, off);
    }
    if (lane == 0) {
        const float inv9 = 1.0f / 9.0f;
        out[w]         = sp * inv9;
        out[BATCH + w] = sn * inv9;
    }
}

extern "C" void kernel_launch(void* const* d_in, const int* in_sizes, int n_in,
                              void* d_out, int out_size) {
    const int*   user     = (const int*)  d_in[0];
    const int*   pos      = (const int*)  d_in[1];
    const int*   neg      = (const int*)  d_in[2];
    const int*   edge_row = (const int*)  d_in[3];
    const int*   edge_col = (const int*)  d_in[4];
    const float* edge_val = (const float*)d_in[5];
    const float* user_emb = (const float*)d_in[6];
    const float* item_emb = (const float*)d_in[7];
    float* out = (float*)d_out;

    // K0a: zero h1 (fp16) + flags + counter
    {
        int total = H1H_WORDS + 2 * FLAG_WORDS;
        k_zero<<<(total + 255) / 256, 256>>>();
    }
    // K0b: batch flags + zero needed h2 rows
    {
        int total = 3 * BATCH * CHUNKS;
        k_flag<<<(total + 255) / 256, 256>>>(user, pos, neg);
    }
    // K0c: fp16 embedding copy
    k_cvt<<<(CVT_GROUPS + 255) / 256, 256>>>((const float4*)user_emb,
                                             (const float4*)item_emb);
    // Compact layer-2 edges (flag[row], ~6% keep) + mark flag2[col]
    k_compactA<<<(COMPACT_THREADS + 255) / 256, 256>>>(edge_row, edge_col, edge_val);
    // SPMM layer 1 over raw edges, inline flag2 filter (fp16 gather+red, ILP=4)
    k_spmm1<<<SPMM1_THREADS / 256, 256>>>(edge_row, edge_col, edge_val);
    // SPMM layer 2 over compacted list
    k_spmm2<<<8192, 256>>>();
    // Scores
    {
        int threads = 256;
        int blocks = (BATCH * 32 + threads - 1) / threads;
        k_score<<<blocks, threads>>>(user, pos, neg,
                                     (const float2*)user_emb, (const float2*)item_emb,
                                     out);
    }
}

// round 11
// speedup vs baseline: 1.1404x; 1.1404x over previous
#include <cuda_runtime.h>
#include <cuda_bf16.h>
#include <cuda_fp16.h>
#include <cuda_fp8.h>
#include <cstdint>

#define NUM_USERS 100000
#define NUM_ITEMS 100000
#define NUM_NODES (NUM_USERS + NUM_ITEMS)
#define EMB_DIM 64
#define NUM_EDGES 4000000
#define BATCH 4096
#define CHUNKS 16   // 16 float4 per node row (fp32 arrays)

// ---- scratch (device globals: allocation-free) ----
__device__ uint4  g_h1h[NUM_NODES * 8];              // fp16 h1: 64 halves/node = 25.6 MB
__device__ float4 g_h2[NUM_NODES * CHUNKS];          // fp32 h2 (only flagged rows valid)
__device__ unsigned char g_embq[NUM_NODES * EMB_DIM];// e4m3 copy of all_emb * 256, 12.8 MB
__device__ unsigned char g_flag[NUM_NODES];          // batch-row flags (layer2 filter)
__device__ unsigned char g_flag2[NUM_NODES];         // needed-h1-row flags (layer1 filter)
__device__ int4 g_l2[NUM_EDGES];                     // packed {row,col,val,0} layer2 edges
__device__ unsigned long long g_p1[NUM_EDGES];       // packed {row:18,col:18,valh:16} layer1
__device__ int g_c2;
__device__ int g_c1;

__device__ __forceinline__ void red_add_v4_f32(float4* addr, float4 v) {
    asm volatile("red.global.add.v4.f32 [%0], {%1, %2, %3, %4};"
                 :: "l"(addr), "f"(v.x), "f"(v.y), "f"(v.z), "f"(v.w)
                 : "memory");
}

// 16B vectorized fp16 reduction: adds 8 halves (4x half2) atomically.
__device__ __forceinline__ void red_add_v4_f16x2(uint4* addr, uint4 v) {
    asm volatile("red.global.add.noftz.v4.f16x2 [%0], {%1, %2, %3, %4};"
                 :: "l"(addr), "r"(v.x), "r"(v.y), "r"(v.z), "r"(v.w)
                 : "memory");
}

// ---- K_init: zero h1h + flags + counters, and build fp8 emb table ----
#define H1H_WORDS (NUM_NODES * 8)                     // 1.6M uint4
#define FLAG_WORDS (NUM_NODES / 16)                   // 12,500 uint4 per flag array
#define CVT8_GROUPS (NUM_NODES * EMB_DIM / 16)        // 800K (16 fp8 per thread)
#define CVT8_USER_GROUPS (NUM_USERS * EMB_DIM / 16)   // 400K
#define INIT_TOTAL (H1H_WORDS + 2 * FLAG_WORDS + CVT8_GROUPS)
__global__ void k_init(const float4* __restrict__ user_emb,
                       const float4* __restrict__ item_emb) {
    int i = blockIdx.x * blockDim.x + threadIdx.x;
    if (i == 0) { g_c1 = 0; g_c2 = 0; }
    if (i < H1H_WORDS) {
        g_h1h[i] = make_uint4(0u, 0u, 0u, 0u);
    } else if (i < H1H_WORDS + FLAG_WORDS) {
        ((uint4*)g_flag)[i - H1H_WORDS] = make_uint4(0u, 0u, 0u, 0u);
    } else if (i < H1H_WORDS + 2 * FLAG_WORDS) {
        ((uint4*)g_flag2)[i - H1H_WORDS - FLAG_WORDS] = make_uint4(0u, 0u, 0u, 0u);
    } else if (i < INIT_TOTAL) {
        int g = i - (H1H_WORDS + 2 * FLAG_WORDS);     // converts 16 floats -> 16 fp8
        const float4* src = (g < CVT8_USER_GROUPS)
            ? (user_emb + (size_t)g * 4)
            : (item_emb + (size_t)(g - CVT8_USER_GROUPS) * 4);
        union { unsigned char b[16]; uint4 u; } o;
        #pragma unroll
        for (int q = 0; q < 4; q++) {
            float4 f = __ldg(src + q);
            o.b[q * 4 + 0] = (unsigned char)__nv_cvt_float_to_fp8(f.x * 256.f, __NV_SATFINITE, __NV_E4M3);
            o.b[q * 4 + 1] = (unsigned char)__nv_cvt_float_to_fp8(f.y * 256.f, __NV_SATFINITE, __NV_E4M3);
            o.b[q * 4 + 2] = (unsigned char)__nv_cvt_float_to_fp8(f.z * 256.f, __NV_SATFINITE, __NV_E4M3);
            o.b[q * 4 + 3] = (unsigned char)__nv_cvt_float_to_fp8(f.w * 256.f, __NV_SATFINITE, __NV_E4M3);
        }
        ((uint4*)g_embq)[g] = o.u;
    }
}

// ---- K_flag: set batch flags (both arrays) + zero those h2 rows ----
__global__ void k_flag(const int* __restrict__ user,
                       const int* __restrict__ pos,
                       const int* __restrict__ neg) {
    int t = blockIdx.x * blockDim.x + threadIdx.x;   // 3*BATCH*16 threads
    int g = t >> 4;
    int c = t & 15;
    if (g >= 3 * BATCH) return;
    int node;
    if (g < BATCH)            node = user[g];
    else if (g < 2 * BATCH)   node = NUM_USERS + pos[g - BATCH];
    else                      node = NUM_USERS + neg[g - 2 * BATCH];
    if (c == 0) { g_flag[node] = 1; g_flag2[node] = 1; }
    g_h2[node * CHUNKS + c] = make_float4(0.f, 0.f, 0.f, 0.f);
}

// ---- K_compactA: layer-2 compaction (keep ~6%) + flag2[col] marking ----
#define COMPACT_THREADS (NUM_EDGES / 4)               // 1,000,000
__global__ void k_compactA(const int* __restrict__ edge_row,
                           const int* __restrict__ edge_col,
                           const float* __restrict__ edge_val) {
    __shared__ int s_cnt;
    __shared__ int s_base;
    __shared__ int s_warp_off[8];

    const int4*   rows4 = (const int4*)edge_row;
    const int4*   cols4 = (const int4*)edge_col;
    const float4* vals4 = (const float4*)edge_val;

    int t = blockIdx.x * blockDim.x + threadIdx.x;
    int lane = threadIdx.x & 31;
    int warp = threadIdx.x >> 5;
    if (threadIdx.x == 0) s_cnt = 0;
    __syncthreads();

    int4 r = make_int4(0, 0, 0, 0), cc = make_int4(0, 0, 0, 0);
    float4 vv = make_float4(0.f, 0.f, 0.f, 0.f);
    bool k0 = false, k1 = false, k2 = false, k3 = false;
    if (t < COMPACT_THREADS) {
        r  = __ldg(rows4 + t);
        k0 = g_flag[r.x] != 0;
        k1 = g_flag[r.y] != 0;
        k2 = g_flag[r.z] != 0;
        k3 = g_flag[r.w] != 0;
        if (k0 | k1 | k2 | k3) {
            cc = __ldg(cols4 + t);
            vv = __ldg(vals4 + t);
            if (k0) g_flag2[cc.x] = 1;
            if (k1) g_flag2[cc.y] = 1;
            if (k2) g_flag2[cc.z] = 1;
            if (k3) g_flag2[cc.w] = 1;
        }
    }
    int n = (int)k0 + (int)k1 + (int)k2 + (int)k3;
    int pre = n;
    #pragma unroll
    for (int o = 1; o < 32; o <<= 1) {
        int x = __shfl_up_sync(0xFFFFFFFFu, pre, o);
        if (lane >= o) pre += x;
    }
    int excl = pre - n;
    int wtot = __shfl_sync(0xFFFFFFFFu, pre, 31);

    if (lane == 31) s_warp_off[warp] = atomicAdd(&s_cnt, wtot);
    __syncthreads();
    if (threadIdx.x == 0) s_base = atomicAdd(&g_c2, s_cnt);
    __syncthreads();

    int p = s_base + s_warp_off[warp] + excl;
    if (k0) g_l2[p++] = make_int4(r.x, cc.x, __float_as_int(vv.x), 0);
    if (k1) g_l2[p++] = make_int4(r.y, cc.y, __float_as_int(vv.y), 0);
    if (k2) g_l2[p++] = make_int4(r.z, cc.z, __float_as_int(vv.z), 0);
    if (k3) g_l2[p++] = make_int4(r.w, cc.w, __float_as_int(vv.w), 0);
}

// ---- K_compactB: layer-1 compaction (keep ~70%), 8B packed records ----
__device__ __forceinline__ unsigned long long pack_edge(int row, int col, float v) {
    unsigned short vh = __half_as_ushort(__float2half(v));
    return (unsigned long long)(unsigned)row
         | ((unsigned long long)(unsigned)col << 18)
         | ((unsigned long long)vh << 36);
}

__global__ void k_compactB(const int* __restrict__ edge_row,
                           const int* __restrict__ edge_col,
                           const float* __restrict__ edge_val) {
    __shared__ int s_cnt;
    __shared__ int s_base;
    __shared__ int s_warp_off[8];

    const int4*   rows4 = (const int4*)edge_row;
    const int4*   cols4 = (const int4*)edge_col;
    const float4* vals4 = (const float4*)edge_val;

    int t = blockIdx.x * blockDim.x + threadIdx.x;
    int lane = threadIdx.x & 31;
    int warp = threadIdx.x >> 5;
    if (threadIdx.x == 0) s_cnt = 0;
    __syncthreads();

    int4 r = make_int4(0, 0, 0, 0), cc = make_int4(0, 0, 0, 0);
    float4 vv = make_float4(0.f, 0.f, 0.f, 0.f);
    bool k0 = false, k1 = false, k2 = false, k3 = false;
    if (t < COMPACT_THREADS) {
        r  = __ldg(rows4 + t);
        cc = __ldg(cols4 + t);
        vv = __ldg(vals4 + t);
        k0 = g_flag2[r.x] != 0;
        k1 = g_flag2[r.y] != 0;
        k2 = g_flag2[r.z] != 0;
        k3 = g_flag2[r.w] != 0;
    }
    int n = (int)k0 + (int)k1 + (int)k2 + (int)k3;
    int pre = n;
    #pragma unroll
    for (int o = 1; o < 32; o <<= 1) {
        int x = __shfl_up_sync(0xFFFFFFFFu, pre, o);
        if (lane >= o) pre += x;
    }
    int excl = pre - n;
    int wtot = __shfl_sync(0xFFFFFFFFu, pre, 31);

    if (lane == 31) s_warp_off[warp] = atomicAdd(&s_cnt, wtot);
    __syncthreads();
    if (threadIdx.x == 0) s_base = atomicAdd(&g_c1, s_cnt);
    __syncthreads();

    int p = s_base + s_warp_off[warp] + excl;
    if (k0) g_p1[p++] = pack_edge(r.x, cc.x, vv.x);
    if (k1) g_p1[p++] = pack_edge(r.y, cc.y, vv.y);
    if (k2) g_p1[p++] = pack_edge(r.z, cc.z, vv.z);
    if (k3) g_p1[p++] = pack_edge(r.w, cc.w, vv.w);
}

// ---- K1: SPMM layer 1 over packed list: h1h[row] += val * embq[col] ----
// 8 lanes/edge: each lane loads 8 fp8 (8B), converts, scales, reds 16B fp16.
#define SPMM1_THREADS (8 * 1024 * 1024)   // * 4 slots = 32M max items (4M edges * 8)
__global__ void k_spmm1(void) {
    long long total = (long long)g_c1 * 8;
    long long t = (long long)blockIdx.x * blockDim.x + threadIdx.x;
    const __half2 inv256 = __float2half2_rn(1.0f / 256.0f);

    #pragma unroll
    for (int k = 0; k < 4; k++) {
        long long item = t + (long long)k * SPMM1_THREADS;
        if (item < total) {
            int idx = (int)(item >> 3);
            int c = (int)(item & 7);
            unsigned long long p = __ldg(&g_p1[idx]);   // broadcast across 8 lanes
            int row = (int)(p & 0x3FFFFull);
            int col = (int)((p >> 18) & 0x3FFFFull);
            __half vh = __ushort_as_half((unsigned short)(p >> 36));
            __half2 vh2 = __half2half2(vh);

            uint2 q = __ldg((const uint2*)(g_embq + ((size_t)col << 6)) + c);
            __half2_raw x0r = __nv_cvt_fp8x2_to_halfraw2((__nv_fp8x2_storage_t)(q.x & 0xFFFF), __NV_E4M3);
            __half2_raw x1r = __nv_cvt_fp8x2_to_halfraw2((__nv_fp8x2_storage_t)(q.x >> 16),    __NV_E4M3);
            __half2_raw x2r = __nv_cvt_fp8x2_to_halfraw2((__nv_fp8x2_storage_t)(q.y & 0xFFFF), __NV_E4M3);
            __half2_raw x3r = __nv_cvt_fp8x2_to_halfraw2((__nv_fp8x2_storage_t)(q.y >> 16),    __NV_E4M3);
            __half2 x0 = *reinterpret_cast<__half2*>(&x0r);
            __half2 x1 = *reinterpret_cast<__half2*>(&x1r);
            __half2 x2 = *reinterpret_cast<__half2*>(&x2r);
            __half2 x3 = *reinterpret_cast<__half2*>(&x3r);
            x0 = __hmul2(__hmul2(x0, vh2), inv256);     // (emb*256 * v) / 256
            x1 = __hmul2(__hmul2(x1, vh2), inv256);
            x2 = __hmul2(__hmul2(x2, vh2), inv256);
            x3 = __hmul2(__hmul2(x3, vh2), inv256);
            uint4 o;
            o.x = *reinterpret_cast<unsigned*>(&x0);
            o.y = *reinterpret_cast<unsigned*>(&x1);
            o.z = *reinterpret_cast<unsigned*>(&x2);
            o.w = *reinterpret_cast<unsigned*>(&x3);
            red_add_v4_f16x2(&g_h1h[((size_t)row << 3) + c], o);
        }
    }
}

// ---- K2: SPMM layer 2: h2[row] += val * h1h[col] (fp16 gather, fp32 red) ----
__global__ void k_spmm2(void) {
    long long total = (long long)g_c2 * CHUNKS;
    long long stride = (long long)gridDim.x * blockDim.x;
    const uint2* h1 = (const uint2*)g_h1h;   // 4 halves per uint2
    for (long long t = (long long)blockIdx.x * blockDim.x + threadIdx.x;
         t < total; t += stride) {
        int idx = (int)(t >> 4);
        int c = (int)(t & 15);
        int4 m = __ldg(&g_l2[idx]);
        float v = __int_as_float(m.z);
        uint2 u = __ldg(&h1[((size_t)m.y << 4) + c]);
        __half2 ha = *reinterpret_cast<__half2*>(&u.x);
        __half2 hb = *reinterpret_cast<__half2*>(&u.y);
        float2 fa = __half22float2(ha);
        float2 fb = __half22float2(hb);
        float4 acc = make_float4(v * fa.x, v * fa.y, v * fb.x, v * fb.y);
        red_add_v4_f32(&g_h2[(size_t)m.x * CHUNKS + c], acc);
    }
}

// ---- K3: gather acc at batch nodes, dot, write scores ----
__global__ void k_score(const int* __restrict__ user,
                        const int* __restrict__ pos,
                        const int* __restrict__ neg,
                        const float2* __restrict__ user_emb2,
                        const float2* __restrict__ item_emb2,
                        float* __restrict__ out) {
    int w = (blockIdx.x * blockDim.x + threadIdx.x) >> 5;
    int lane = threadIdx.x & 31;
    if (w >= BATCH) return;
    int nu = user[w];
    int np = NUM_USERS + pos[w];
    int nn = NUM_USERS + neg[w];

    const unsigned* h1u = (const unsigned*)g_h1h;   // 2 halves per word
    const float2* h2 = (const float2*)g_h2;
    const int L = EMB_DIM / 2;

    unsigned w1u = __ldg(&h1u[(size_t)nu * L + lane]);
    __half2 hu = *reinterpret_cast<__half2*>(&w1u);
    float2 u1 = __half22float2(hu);
    float2 ue = user_emb2[(size_t)nu * L + lane];
    float2 u2 = h2[(size_t)nu * L + lane];
    float ux = ue.x + u1.x + u2.x;
    float uy = ue.y + u1.y + u2.y;

    unsigned w1p = __ldg(&h1u[(size_t)np * L + lane]);
    __half2 hp = *reinterpret_cast<__half2*>(&w1p);
    float2 p1 = __half22float2(hp);
    float2 pe = item_emb2[(size_t)(np - NUM_USERS) * L + lane];
    float2 p2 = h2[(size_t)np * L + lane];
    float px = pe.x + p1.x + p2.x;
    float py = pe.y + p1.y + p2.y;

    unsigned w1n = __ldg(&h1u[(size_t)nn * L + lane]);
    __half2 hn = *reinterpret_cast<__half2*>(&w1n);
    float2 n1 = __half22float2(hn);
    float2 ne = item_emb2[(size_t)(nn - NUM_USERS) * L + lane];
    float2 n2 = h2[(size_t)nn * L + lane];
    float nx = ne.x + n1.x + n2.x;
    float ny = ne.y + n1.y + n2.y;

    float sp = ux * px + uy * py;
    float sn = ux * nx + uy * ny;
    #pragma unroll
    for (int off = 16; off > 0; off >>= 1) {
        sp += __shfl_xor_sync(0xFFFFFFFFu, sp, off);
        sn += __shfl_xor_sync(0xFFFFFFFFu, sn, off);
    }
    if (lane == 0) {
        const float inv9 = 1.0f / 9.0f;
        out[w]         = sp * inv9;
        out[BATCH + w] = sn * inv9;
    }
}

extern "C" void kernel_launch(void* const* d_in, const int* in_sizes, int n_in,
                              void* d_out, int out_size) {
    const int*   user     = (const int*)  d_in[0];
    const int*   pos      = (const int*)  d_in[1];
    const int*   neg      = (const int*)  d_in[2];
    const int*   edge_row = (const int*)  d_in[3];
    const int*   edge_col = (const int*)  d_in[4];
    const float* edge_val = (const float*)d_in[5];
    const float* user_emb = (const float*)d_in[6];
    const float* item_emb = (const float*)d_in[7];
    float* out = (float*)d_out;

    // Init: zero h1h/flags/counters + build fp8 emb table
    k_init<<<(INIT_TOTAL + 255) / 256, 256>>>((const float4*)user_emb,
                                              (const float4*)item_emb);
    // Batch flags + zero needed h2 rows
    {
        int total = 3 * BATCH * CHUNKS;
        k_flag<<<(total + 255) / 256, 256>>>(user, pos, neg);
    }
    // Compact layer-2 edges (flag[row], ~6% keep) + mark flag2[col]
    k_compactA<<<(COMPACT_THREADS + 255) / 256, 256>>>(edge_row, edge_col, edge_val);
    // Compact layer-1 edges (flag2[row], ~70% keep) into 8B packed records
    k_compactB<<<(COMPACT_THREADS + 255) / 256, 256>>>(edge_row, edge_col, edge_val);
    // SPMM layer 1 (fp8 gather + fp16 vector red, ILP=4)
    k_spmm1<<<SPMM1_THREADS / 256, 256>>>();
    // SPMM layer 2 over compacted list
    k_spmm2<<<8192, 256>>>();
    // Scores
    {
        int threads = 256;
        int blocks = (BATCH * 32 + threads - 1) / threads;
        k_score<<<blocks, threads>>>(user, pos, neg,
                                     (const float2*)user_emb, (const float2*)item_emb,
                                     out);
    }
}

// round 14
// speedup vs baseline: 1.1566x; 1.0142x over previous
#include <cuda_runtime.h>
#include <cuda_bf16.h>
#include <cuda_fp16.h>
#include <cstdint>

#define NUM_USERS 100000
#define NUM_ITEMS 100000
#define NUM_NODES (NUM_USERS + NUM_ITEMS)
#define EMB_DIM 64
#define NUM_EDGES 4000000
#define BATCH 4096
#define CHUNKS 16   // 16 float4 per node row (fp32 arrays)

// bitmask flags: 200000 bits -> 6250 words, padded to 6256 (uint4 multiple)
#define FB_WORDS 6256
#define FB_U4 (FB_WORDS / 4)

// ---- scratch (device globals: allocation-free) ----
__device__ uint4  g_h1h[NUM_NODES * 8];              // fp16 h1: 64 halves/node = 25.6 MB
__device__ float4 g_h2[NUM_NODES * CHUNKS];          // fp32 h2 (only flagged rows valid)
__device__ uint4  g_embh[NUM_NODES * 8];             // fp16 copy of all_emb, 25.6 MB
__device__ unsigned g_fbA[FB_WORDS];                 // batch-row bitmask (layer2 filter)
__device__ unsigned g_fbB[FB_WORDS];                 // needed-h1-row bitmask (layer1 filter)
__device__ int4 g_l2[NUM_EDGES];                     // packed {row,col,val,0} layer2 edges
__device__ unsigned long long g_p1[NUM_EDGES];       // packed {row:18,col:18,valh:16} layer1
__device__ int g_c2;
__device__ int g_c1;

__device__ __forceinline__ void red_add_v4_f32(float4* addr, float4 v) {
    asm volatile("red.global.add.v4.f32 [%0], {%1, %2, %3, %4};"
                 :: "l"(addr), "f"(v.x), "f"(v.y), "f"(v.z), "f"(v.w)
                 : "memory");
}

// 16B vectorized fp16 reduction: adds 8 halves (4x half2) atomically.
__device__ __forceinline__ void red_add_v4_f16x2(uint4* addr, uint4 v) {
    asm volatile("red.global.add.noftz.v4.f16x2 [%0], {%1, %2, %3, %4};"
                 :: "l"(addr), "r"(v.x), "r"(v.y), "r"(v.z), "r"(v.w)
                 : "memory");
}

__device__ __forceinline__ bool test_bit(const unsigned* fb, int n) {
    return (__ldg(fb + (n >> 5)) >> (n & 31)) & 1u;
}

// ---- K_init: zero h1h + bitmasks + counters, and build fp16 emb table ----
#define H1H_WORDS (NUM_NODES * 8)                     // 1.6M uint4
#define CVT_GROUPS (NUM_NODES * EMB_DIM / 8)          // 1.6M (8 floats per thread)
#define CVT_USER_GROUPS (NUM_USERS * EMB_DIM / 8)     // 800K
#define INIT_TOTAL (H1H_WORDS + 2 * FB_U4 + CVT_GROUPS)
__global__ void k_init(const float4* __restrict__ user_emb,
                       const float4* __restrict__ item_emb) {
    int i = blockIdx.x * blockDim.x + threadIdx.x;
    if (i == 0) { g_c1 = 0; g_c2 = 0; }
    if (i < H1H_WORDS) {
        g_h1h[i] = make_uint4(0u, 0u, 0u, 0u);
    } else if (i < H1H_WORDS + FB_U4) {
        ((uint4*)g_fbA)[i - H1H_WORDS] = make_uint4(0u, 0u, 0u, 0u);
    } else if (i < H1H_WORDS + 2 * FB_U4) {
        ((uint4*)g_fbB)[i - H1H_WORDS - FB_U4] = make_uint4(0u, 0u, 0u, 0u);
    } else if (i < INIT_TOTAL) {
        int g = i - (H1H_WORDS + 2 * FB_U4);
        const float4* src = (g < CVT_USER_GROUPS)
            ? (user_emb + (size_t)g * 2)
            : (item_emb + (size_t)(g - CVT_USER_GROUPS) * 2);
        float4 a = __ldg(src);
        float4 b = __ldg(src + 1);
        __half2 h0 = __floats2half2_rn(a.x, a.y);
        __half2 h1 = __floats2half2_rn(a.z, a.w);
        __half2 h2 = __floats2half2_rn(b.x, b.y);
        __half2 h3 = __floats2half2_rn(b.z, b.w);
        uint4 o;
        o.x = *reinterpret_cast<unsigned*>(&h0);
        o.y = *reinterpret_cast<unsigned*>(&h1);
        o.z = *reinterpret_cast<unsigned*>(&h2);
        o.w = *reinterpret_cast<unsigned*>(&h3);
        g_embh[g] = o;
    }
}

// ---- K_flag: set batch bits (both masks) + zero those h2 rows ----
__global__ void k_flag(const int* __restrict__ user,
                       const int* __restrict__ pos,
                       const int* __restrict__ neg) {
    int t = blockIdx.x * blockDim.x + threadIdx.x;   // 3*BATCH*16 threads
    int g = t >> 4;
    int c = t & 15;
    if (g >= 3 * BATCH) return;
    int node;
    if (g < BATCH)            node = user[g];
    else if (g < 2 * BATCH)   node = NUM_USERS + pos[g - BATCH];
    else                      node = NUM_USERS + neg[g - 2 * BATCH];
    if (c == 0) {
        unsigned bit = 1u << (node & 31);
        atomicOr(&g_fbA[node >> 5], bit);
        atomicOr(&g_fbB[node >> 5], bit);
    }
    g_h2[node * CHUNKS + c] = make_float4(0.f, 0.f, 0.f, 0.f);
}

// ---- K_compactA: layer-2 compaction (keep ~6%) + fbB[col] marking ----
#define COMPACT_THREADS (NUM_EDGES / 4)               // 1,000,000
__global__ void k_compactA(const int* __restrict__ edge_row,
                           const int* __restrict__ edge_col,
                           const float* __restrict__ edge_val) {
    __shared__ int s_cnt;
    __shared__ int s_base;
    __shared__ int s_warp_off[8];

    const int4*   rows4 = (const int4*)edge_row;
    const int4*   cols4 = (const int4*)edge_col;
    const float4* vals4 = (const float4*)edge_val;

    int t = blockIdx.x * blockDim.x + threadIdx.x;
    int lane = threadIdx.x & 31;
    int warp = threadIdx.x >> 5;
    if (threadIdx.x == 0) s_cnt = 0;
    __syncthreads();

    int4 r = make_int4(0, 0, 0, 0), cc = make_int4(0, 0, 0, 0);
    float4 vv = make_float4(0.f, 0.f, 0.f, 0.f);
    bool k0 = false, k1 = false, k2 = false, k3 = false;
    if (t < COMPACT_THREADS) {
        r  = __ldg(rows4 + t);
        k0 = test_bit(g_fbA, r.x);
        k1 = test_bit(g_fbA, r.y);
        k2 = test_bit(g_fbA, r.z);
        k3 = test_bit(g_fbA, r.w);
        if (k0 | k1 | k2 | k3) {
            cc = __ldg(cols4 + t);
            vv = __ldg(vals4 + t);
            if (k0) atomicOr(&g_fbB[cc.x >> 5], 1u << (cc.x & 31));
            if (k1) atomicOr(&g_fbB[cc.y >> 5], 1u << (cc.y & 31));
            if (k2) atomicOr(&g_fbB[cc.z >> 5], 1u << (cc.z & 31));
            if (k3) atomicOr(&g_fbB[cc.w >> 5], 1u << (cc.w & 31));
        }
    }
    int n = (int)k0 + (int)k1 + (int)k2 + (int)k3;
    int pre = n;
    #pragma unroll
    for (int o = 1; o < 32; o <<= 1) {
        int x = __shfl_up_sync(0xFFFFFFFFu, pre, o);
        if (lane >= o) pre += x;
    }
    int excl = pre - n;
    int wtot = __shfl_sync(0xFFFFFFFFu, pre, 31);

    if (lane == 31) s_warp_off[warp] = atomicAdd(&s_cnt, wtot);
    __syncthreads();
    if (threadIdx.x == 0) s_base = atomicAdd(&g_c2, s_cnt);
    __syncthreads();

    int p = s_base + s_warp_off[warp] + excl;
    if (k0) g_l2[p++] = make_int4(r.x, cc.x, __float_as_int(vv.x), 0);
    if (k1) g_l2[p++] = make_int4(r.y, cc.y, __float_as_int(vv.y), 0);
    if (k2) g_l2[p++] = make_int4(r.z, cc.z, __float_as_int(vv.z), 0);
    if (k3) g_l2[p++] = make_int4(r.w, cc.w, __float_as_int(vv.w), 0);
}

// ---- K_compactB: layer-1 compaction (keep ~70%), 8B packed records ----
__device__ __forceinline__ unsigned long long pack_edge(int row, int col, float v) {
    unsigned short vh = __half_as_ushort(__float2half(v));
    return (unsigned long long)(unsigned)row
         | ((unsigned long long)(unsigned)col << 18)
         | ((unsigned long long)vh << 36);
}

__global__ void k_compactB(const int* __restrict__ edge_row,
                           const int* __restrict__ edge_col,
                           const float* __restrict__ edge_val) {
    __shared__ int s_cnt;
    __shared__ int s_base;
    __shared__ int s_warp_off[8];

    const int4*   rows4 = (const int4*)edge_row;
    const int4*   cols4 = (const int4*)edge_col;
    const float4* vals4 = (const float4*)edge_val;

    int t = blockIdx.x * blockDim.x + threadIdx.x;
    int lane = threadIdx.x & 31;
    int warp = threadIdx.x >> 5;
    if (threadIdx.x == 0) s_cnt = 0;
    __syncthreads();

    int4 r = make_int4(0, 0, 0, 0), cc = make_int4(0, 0, 0, 0);
    float4 vv = make_float4(0.f, 0.f, 0.f, 0.f);
    bool k0 = false, k1 = false, k2 = false, k3 = false;
    if (t < COMPACT_THREADS) {
        r  = __ldg(rows4 + t);
        cc = __ldg(cols4 + t);
        vv = __ldg(vals4 + t);
        k0 = test_bit(g_fbB, r.x);
        k1 = test_bit(g_fbB, r.y);
        k2 = test_bit(g_fbB, r.z);
        k3 = test_bit(g_fbB, r.w);
    }
    int n = (int)k0 + (int)k1 + (int)k2 + (int)k3;
    int pre = n;
    #pragma unroll
    for (int o = 1; o < 32; o <<= 1) {
        int x = __shfl_up_sync(0xFFFFFFFFu, pre, o);
        if (lane >= o) pre += x;
    }
    int excl = pre - n;
    int wtot = __shfl_sync(0xFFFFFFFFu, pre, 31);

    if (lane == 31) s_warp_off[warp] = atomicAdd(&s_cnt, wtot);
    __syncthreads();
    if (threadIdx.x == 0) s_base = atomicAdd(&g_c1, s_cnt);
    __syncthreads();

    int p = s_base + s_warp_off[warp] + excl;
    if (k0) g_p1[p++] = pack_edge(r.x, cc.x, vv.x);
    if (k1) g_p1[p++] = pack_edge(r.y, cc.y, vv.y);
    if (k2) g_p1[p++] = pack_edge(r.z, cc.z, vv.z);
    if (k3) g_p1[p++] = pack_edge(r.w, cc.w, vv.w);
}

// ---- K1: SPMM layer 1 over packed list: h1h[row] += val * embh[col] ----
// 8 lanes/edge: lane loads 16B (8 fp16), scales, reds 16B fp16. ILP=4.
#define SPMM1_THREADS (8 * 1024 * 1024)   // * 4 slots = 32M max items (4M edges * 8)
__global__ void k_spmm1(void) {
    long long total = (long long)g_c1 * 8;
    long long t = (long long)blockIdx.x * blockDim.x + threadIdx.x;

    #pragma unroll
    for (int k = 0; k < 4; k++) {
        long long item = t + (long long)k * SPMM1_THREADS;
        if (item < total) {
            int idx = (int)(item >> 3);
            int c = (int)(item & 7);
            unsigned long long p = __ldg(&g_p1[idx]);   // broadcast across 8 lanes
            int row = (int)(p & 0x3FFFFull);
            int col = (int)((p >> 18) & 0x3FFFFull);
            __half vh = __ushort_as_half((unsigned short)(p >> 36));
            __half2 vh2 = __half2half2(vh);

            uint4 u = __ldg(&g_embh[((size_t)col << 3) + c]);
            __half2 a = *reinterpret_cast<__half2*>(&u.x);
            __half2 b = *reinterpret_cast<__half2*>(&u.y);
            __half2 d = *reinterpret_cast<__half2*>(&u.z);
            __half2 e = *reinterpret_cast<__half2*>(&u.w);
            a = __hmul2(a, vh2);
            b = __hmul2(b, vh2);
            d = __hmul2(d, vh2);
            e = __hmul2(e, vh2);
            uint4 o;
            o.x = *reinterpret_cast<unsigned*>(&a);
            o.y = *reinterpret_cast<unsigned*>(&b);
            o.z = *reinterpret_cast<unsigned*>(&d);
            o.w = *reinterpret_cast<unsigned*>(&e);
            red_add_v4_f16x2(&g_h1h[((size_t)row << 3) + c], o);
        }
    }
}

// ---- K2: SPMM layer 2: h2[row] += val * h1h[col] (fp16 gather, fp32 red) ----
__global__ void k_spmm2(void) {
    long long total = (long long)g_c2 * CHUNKS;
    long long stride = (long long)gridDim.x * blockDim.x;
    const uint2* h1 = (const uint2*)g_h1h;   // 4 halves per uint2
    for (long long t = (long long)blockIdx.x * blockDim.x + threadIdx.x;
         t < total; t += stride) {
        int idx = (int)(t >> 4);
        int c = (int)(t & 15);
        int4 m = __ldg(&g_l2[idx]);
        float v = __int_as_float(m.z);
        uint2 u = __ldg(&h1[((size_t)m.y << 4) + c]);
        __half2 ha = *reinterpret_cast<__half2*>(&u.x);
        __half2 hb = *reinterpret_cast<__half2*>(&u.y);
        float2 fa = __half22float2(ha);
        float2 fb = __half22float2(hb);
        float4 acc = make_float4(v * fa.x, v * fa.y, v * fb.x, v * fb.y);
        red_add_v4_f32(&g_h2[(size_t)m.x * CHUNKS + c], acc);
    }
}

// ---- K3: gather acc at batch nodes, dot, write scores ----
__global__ void k_score(const int* __restrict__ user,
                        const int* __restrict__ pos,
                        const int* __restrict__ neg,
                        const float2* __restrict__ user_emb2,
                        const float2* __restrict__ item_emb2,
                        float* __restrict__ out) {
    int w = (blockIdx.x * blockDim.x + threadIdx.x) >> 5;
    int lane = threadIdx.x & 31;
    if (w >= BATCH) return;
    int nu = user[w];
    int np = NUM_USERS + pos[w];
    int nn = NUM_USERS + neg[w];

    const unsigned* h1u = (const unsigned*)g_h1h;   // 2 halves per word
    const float2* h2 = (const float2*)g_h2;
    const int L = EMB_DIM / 2;

    unsigned w1u = __ldg(&h1u[(size_t)nu * L + lane]);
    __half2 hu = *reinterpret_cast<__half2*>(&w1u);
    float2 u1 = __half22float2(hu);
    float2 ue = user_emb2[(size_t)nu * L + lane];
    float2 u2 = h2[(size_t)nu * L + lane];
    float ux = ue.x + u1.x + u2.x;
    float uy = ue.y + u1.y + u2.y;

    unsigned w1p = __ldg(&h1u[(size_t)np * L + lane]);
    __half2 hp = *reinterpret_cast<__half2*>(&w1p);
    float2 p1 = __half22float2(hp);
    float2 pe = item_emb2[(size_t)(np - NUM_USERS) * L + lane];
    float2 p2 = h2[(size_t)np * L + lane];
    float px = pe.x + p1.x + p2.x;
    float py = pe.y + p1.y + p2.y;

    unsigned w1n = __ldg(&h1u[(size_t)nn * L + lane]);
    __half2 hn = *reinterpret_cast<__half2*>(&w1n);
    float2 n1 = __half22float2(hn);
    float2 ne = item_emb2[(size_t)(nn - NUM_USERS) * L + lane];
    float2 n2 = h2[(size_t)nn * L + lane];
    float nx = ne.x + n1.x + n2.x;
    float ny = ne.y + n1.y + n2.y;

    float sp = ux * px + uy * py;
    float sn = ux * nx + uy * ny;
    #pragma unroll
    for (int off = 16; off > 0; off >>= 1) {
        sp += __shfl_xor_sync(0xFFFFFFFFu, sp, off);
        sn += __shfl_xor_sync(0xFFFFFFFFu, sn, off);
    }
    if (lane == 0) {
        const float inv9 = 1.0f / 9.0f;
        out[w]         = sp * inv9;
        out[BATCH + w] = sn * inv9;
    }
}

extern "C" void kernel_launch(void* const* d_in, const int* in_sizes, int n_in,
                              void* d_out, int out_size) {
    const int*   user     = (const int*)  d_in[0];
    const int*   pos      = (const int*)  d_in[1];
    const int*   neg      = (const int*)  d_in[2];
    const int*   edge_row = (const int*)  d_in[3];
    const int*   edge_col = (const int*)  d_in[4];
    const float* edge_val = (const float*)d_in[5];
    const float* user_emb = (const float*)d_in[6];
    const float* item_emb = (const float*)d_in[7];
    float* out = (float*)d_out;

    // Init: zero h1h/bitmasks/counters + build fp16 emb table
    k_init<<<(INIT_TOTAL + 255) / 256, 256>>>((const float4*)user_emb,
                                              (const float4*)item_emb);
    // Batch flag bits + zero needed h2 rows
    {
        int total = 3 * BATCH * CHUNKS;
        k_flag<<<(total + 255) / 256, 256>>>(user, pos, neg);
    }
    // Compact layer-2 edges (bitmask filter, ~6% keep) + mark fbB[col]
    k_compactA<<<(COMPACT_THREADS + 255) / 256, 256>>>(edge_row, edge_col, edge_val);
    // Compact layer-1 edges (bitmask filter, ~70% keep) into 8B packed records
    k_compactB<<<(COMPACT_THREADS + 255) / 256, 256>>>(edge_row, edge_col, edge_val);
    // SPMM layer 1 (fp16 gather + fp16 vector red, ILP=4)
    k_spmm1<<<SPMM1_THREADS / 256, 256>>>();
    // SPMM layer 2 over compacted list
    k_spmm2<<<8192, 256>>>();
    // Scores
    {
        int threads = 256;
        int blocks = (BATCH * 32 + threads - 1) / threads;
        k_score<<<blocks, threads>>>(user, pos, neg,
                                     (const float2*)user_emb, (const float2*)item_emb,
                                     out);
    }
}